// round 16
// baseline (speedup 1.0000x reference)
#include <cuda_runtime.h>

// DistanceTransformMap: exact EDT + approx-sqrt (rel err ~2^-23 << 1e-3).
// SINGLE kernel: phase 1 ballot-compress -> per-batch grid barrier ->
// phase 2 funnels + column search.
//
// R16: occupancy fix. All prior variants were GRID-limited to 31 warps/SM
// (48% occ) with warps ~97% latency-stalled. Now CPB=2 -> GRID=768, NT=384,
// occ 5 (60 warps/SM): per-thread work halves, resident warps double.
// Deadlock-safe: batches 0-2 (blocks 0-575) are fully wave-1 resident
// (capacity 148x5=740) and retire, freeing slots for batch 3's tail blocks.
//
// Exactness of the EDT (before sqrt):
//  - funnel covers >=33 bits each direction; empty window -> exact word loop;
//    zero word-pads make boundaries exact; no zero in row -> d>=384 -> LARGE
//    (matches reference: min attained at j=i is LARGE).
//  - near window d<=4 unconditional: extra candidates are upper bounds.
//  - far case (best>25): clamped indices land on LARGE pads (left slots 0..7,
//    right 392..399); LARGE + d^2 > LARGE >= best0 never wins.
// All EDT intermediates are exact integers < 2^24 in fp32.

constexpr int Bn = 4;
constexpr int Hn = 384;
constexpr int Wn = 384;
constexpr int N  = 384;
constexpr int JW = 14;                        // 12 words + 2 zero pads
constexpr float LARGE = 2.0f * (float)(Hn * Hn + Wn * Wn);  // 589824 > 383^2

constexpr int PAD = 8;
constexpr int LWD = N + 2 * PAD;              // 400 valid slots
constexpr int LWP = 404;                      // line stride (16B-aligned)
constexpr int CPB = 2;                        // columns per block
constexpr int NT  = 384;
constexpr int SPB = Wn / CPB;                 // 192 blocks per batch
constexpr int GRID = Bn * SPB;                // 768

__device__ unsigned g_bm_t[Bn * JW * Hn];
__device__ unsigned g_cnt[Bn];                // per-batch arrival counters
__device__ unsigned g_flag[Bn];               // per-batch generation flags

__device__ __forceinline__ float sqrt_approx(float x) {
    float r;
    asm("sqrt.approx.f32 %0, %1;" : "=f"(r) : "f"(x));
    return r;
}

__device__ __forceinline__ float near_far(const float* __restrict__ row,
                                          float best, int i) {
    float df = 5.0f;
    int d = 5;
    const int ip = i + PAD;
    while (df * df < best && d < N) {
#pragma unroll
        for (int u = 0; u < 4; ++u) {
            const int jr = min(ip + d + u, LWD - 1);
            const int jl = max(ip - d - u, 0);
            const float e = df + (float)u;
            best = fminf(best, fmaf(e, e, fminf(row[jr], row[jl])));
        }
        df += 4.0f;
        d += 4;
    }
    return best;
}

// Per-batch barrier: scoped one-thread release/acquire, monotonic flag.
__device__ __forceinline__ void batch_barrier(int bb) {
    __syncthreads();                           // block stores visible to t0
    if (threadIdx.x == 0) {
        unsigned old;
        asm volatile("atom.acq_rel.gpu.add.u32 %0, [%1], 1;"
                     : "=r"(old) : "l"(&g_cnt[bb]) : "memory");
        const unsigned target = old / (unsigned)SPB + 1u;
        if ((old % (unsigned)SPB) == (unsigned)(SPB - 1)) {
            asm volatile("red.release.gpu.max.u32 [%0], %1;"
                         :: "l"(&g_flag[bb]), "r"(target) : "memory");
        } else {
            unsigned cur;
            while (true) {
                asm volatile("ld.acquire.gpu.u32 %0, [%1];"
                             : "=r"(cur) : "l"(&g_flag[bb]) : "memory");
                if (cur >= target) break;
                __nanosleep(32);
            }
        }
    }
    __syncthreads();
}

__global__ __launch_bounds__(NT, 5) void edt_all(const float* __restrict__ mask,
                                                 float* __restrict__ out) {
    __shared__ unsigned sh_t[3 * Hn];                 // word-slabs [q][y]
    __shared__ __align__(16) float lines[CPB * LWP];  // 2 padded column-lines

    const int t = threadIdx.x;
    const int w = t >> 5, lane = t & 31;
    const int b = blockIdx.x / SPB;            // batch (phase 1 AND phase 2)
    const int x0 = (blockIdx.x - b * SPB) * CPB;

    // ---- Phase 1: compress 2 rows of my batch (non-redundant) ----
    {
        const int row_k = w & 1;               // which of my 2 rows
        const int grp = w >> 1;                // word pair 0..5
        const int L = blockIdx.x * 2 + row_k;  // rows 384b .. 384b+383
        const int y1 = L - b * Hn;
        unsigned* __restrict__ dstb = g_bm_t + (size_t)b * JW * Hn;
        const float* __restrict__ srow = mask + (size_t)L * N;
#pragma unroll
        for (int u = 0; u < 2; ++u) {
            const int j = grp * 2 + u;
            const float v = srow[j * 32 + lane];
            const unsigned m = __ballot_sync(0xffffffffu, v <= 0.5f);
            if (lane == j) dstb[(j + 1) * Hn + y1] = m;
        }
        if (grp == 0) {                        // zero word-pads for this row
            if (lane == 12) dstb[y1] = 0u;
            if (lane == 13) dstb[13 * Hn + y1] = 0u;
        }
    }
    // Overlap: LARGE pads for the 2 column lines.
    if (t < CPB * PAD) {
        const int c = t >> 3, o = t & 7;
        lines[c * LWP + o] = LARGE;
        lines[c * LWP + LWD - PAD + o] = LARGE;
    }

    batch_barrier(b);                          // batch b's bitmap visible

    // ---- Phase 2 ----
    const int jw = x0 >> 5;                    // bp0 = x0&31 <= 30 (+1 <= 31)
    const unsigned* __restrict__ src = g_bm_t + ((size_t)b * JW + jw) * Hn;
#pragma unroll
    for (int r = 0; r < 3; ++r)
        sh_t[t + NT * r] = src[t + NT * r];    // contiguous, L2-hot
    __syncthreads();

    {   // row distances: thread owns y=t, 2 columns via funnels
        const int y = t;
        const unsigned wm1 = sh_t[y];
        const unsigned w0  = sh_t[Hn + y];
        const unsigned wp1 = sh_t[2 * Hn + y];
        const unsigned long long vr = ((unsigned long long)wp1 << 32) | w0;
        const unsigned long long vl = ((unsigned long long)w0 << 32) | wm1;
        const int bp0 = x0 & 31;
        const unsigned* __restrict__ gfb = g_bm_t + (size_t)b * JW * Hn;
#pragma unroll
        for (int xl = 0; xl < CPB; ++xl) {
            const int bp = bp0 + xl;           // <= 31
            const int xg = x0 + xl;
            int dr, dl;
            const unsigned long long r64 = vr >> bp;
            if (r64) {
                dr = __ffsll(r64) - 1;
            } else {                            // rare exact fallback
                dr = 0x7fff;
                for (int j = jw + 2; j < 12; ++j) {
                    const unsigned uu = gfb[(j + 1) * Hn + y];
                    if (uu) { dr = j * 32 - xg + __ffs(uu) - 1; break; }
                }
            }
            const unsigned long long l64 = vl << (31 - bp);
            if (l64) {
                dl = __clzll(l64);
            } else {
                dl = 0x7fff;
                for (int j = jw - 2; j >= 0; --j) {
                    const unsigned uu = gfb[(j + 1) * Hn + y];
                    if (uu) { dl = xg - j * 32 - 31 + __clz(uu); break; }
                }
            }
            const int d = min(dl, dr);
            lines[xl * LWP + PAD + y] = (d < 384) ? (float)(d * d) : LARGE;
        }
    }
    __syncthreads();

    // ---- Column search: 2 searches/thread, shared aligned 12-float window.
    // warp -> (column cl, segment seg); k0 = seg*32+lane in [0,192);
    // pair p = k0>>1 owns window [4p-4, 4p+7] (3 aligned LDS.128, broadcast
    // within the pair); sub = k0&1 selects y = 4p+2sub+{0,1} via a static
    // 10-float shifted view (FSELs, no dynamic indexing).
    const int cl = w & 1, seg = w >> 1;        // seg 0..5
    const int k0 = seg * 32 + lane;            // 0..191
    const int p = k0 >> 1, sub = k0 & 1;
    const float* __restrict__ row = &lines[cl * LWP];

    const float4* __restrict__ vp =
        reinterpret_cast<const float4*>(row + PAD - 4 + 4 * p);
    const float4 A = vp[0], Bq = vp[1], Cq = vp[2];
    const float v[12] = {A.x, A.y, A.z, A.w, Bq.x, Bq.y, Bq.z, Bq.w,
                         Cq.x, Cq.y, Cq.z, Cq.w};
    const bool s1 = (sub != 0);
    float u0 = s1 ? v[2] : v[0];
    float u1 = s1 ? v[3] : v[1];
    float u2 = s1 ? v[4] : v[2];
    float u3 = s1 ? v[5] : v[3];
    float u4 = s1 ? v[6] : v[4];
    float u5 = s1 ? v[7] : v[5];
    float u6 = s1 ? v[8] : v[6];
    float u7 = s1 ? v[9] : v[7];
    float u8 = s1 ? v[10] : v[8];
    float u9 = s1 ? v[11] : v[9];

    // search j=0 at y0 = 4p+2sub (center u4), j=1 at y0+1 (center u5)
    float b0, b1;
    {
        const float c1 = fminf(u3, u5) + 1.0f;
        const float c2 = fminf(u2, u6) + 4.0f;
        const float c3 = fminf(u1, u7) + 9.0f;
        const float c4 = fminf(u0, u8) + 16.0f;
        b0 = fminf(u4, fminf(fminf(c1, c2), fminf(c3, c4)));
    }
    {
        const float c1 = fminf(u4, u6) + 1.0f;
        const float c2 = fminf(u3, u7) + 4.0f;
        const float c3 = fminf(u2, u8) + 9.0f;
        const float c4 = fminf(u1, u9) + 16.0f;
        b1 = fminf(u5, fminf(fminf(c1, c2), fminf(c3, c4)));
    }
    const int y0 = 4 * p + 2 * sub;
    if (fmaxf(b0, b1) > 25.0f) {               // rare refinement
        if (b0 > 25.0f) b0 = near_far(row, b0, y0);
        if (b1 > 25.0f) b1 = near_far(row, b1, y0 + 1);
    }

    // Direct stores (no staging): L2 write-coalesces sectors across blocks.
    float* __restrict__ dst = out + ((size_t)b * Hn + y0) * Wn + x0 + cl;
    dst[0]  = sqrt_approx(b0);
    dst[Wn] = sqrt_approx(b1);
}

extern "C" void kernel_launch(void* const* d_in, const int* in_sizes, int n_in,
                              void* d_out, int out_size) {
    const float* mask = (const float*)d_in[0];
    float* out = (float*)d_out;
    (void)in_sizes; (void)n_in; (void)out_size;

    edt_all<<<GRID, NT>>>(mask, out);
}

// round 17
// speedup vs baseline: 1.4431x; 1.4431x over previous
#include <cuda_runtime.h>

// DistanceTransformMap: exact EDT + approx-sqrt (rel err ~2^-23 << 1e-3).
// TWO kernels (R16 showed fused+barrier convoys the grid; two-kernel R10
// structure is the proven best), with the main kernel split fine (CPB=2,
// grid=768, occ 6 -> ~62 warps/SM, single wave, no inter-block coupling).
//
// Kernel 1: ballot-compress zero-pixel bitmap, TRANSPOSED g_bm_t[b][j+1][y]
//           with zero word-pad columns 0 and 13.
// Kernel 2: per-(batch, 2-column strip): load word-slabs jw-1..jw+1
//           (contiguous, L2-hot), row distances via 64-bit funnel bit-scans,
//           column search via pair-shared aligned 12-float windows.
//
// Exactness of the EDT (before sqrt):
//  - funnel covers >=33 bits each direction; empty window -> exact word loop;
//    zero word-pads make boundaries exact; no zero in row -> d>=384 -> LARGE
//    (matches reference: min attained at j=i is LARGE).
//  - near window d<=4 unconditional: extra candidates are upper bounds.
//  - far case (best>25): clamped indices land on LARGE pads (left slots 0..7,
//    right 392..399); LARGE + d^2 > LARGE >= best0 never wins.
// All EDT intermediates are exact integers < 2^24 in fp32.

constexpr int Bn = 4;
constexpr int Hn = 384;
constexpr int Wn = 384;
constexpr int N  = 384;
constexpr int JW = 14;                        // 12 words + 2 zero pads
constexpr float LARGE = 2.0f * (float)(Hn * Hn + Wn * Wn);  // 589824 > 383^2

constexpr int PAD = 8;
constexpr int LWD = N + 2 * PAD;              // 400 valid slots
constexpr int LWP = 404;                      // line stride (16B-aligned)
constexpr int CPB = 2;                        // columns per main block
constexpr int NT  = 384;
constexpr int SPB = Wn / CPB;                 // 192 strips per batch
constexpr int GRID2 = Bn * SPB;               // 768 (single wave at occ 6)

__device__ unsigned g_bm_t[Bn * JW * Hn];

// ---------------- Kernel 1: ballot compress (transposed) ----------------
__global__ __launch_bounds__(384) void edt_compress(const float* __restrict__ mask) {
    const int w = threadIdx.x >> 5, lane = threadIdx.x & 31;
    const int L = blockIdx.x * 12 + w;        // blocks never straddle batches
    const int b = L / Hn, y = L - b * Hn;
    const size_t base = (size_t)L * N;
    unsigned* __restrict__ dstb = g_bm_t + (size_t)b * JW * Hn;
#pragma unroll
    for (int k = 0; k < 12; ++k) {
        const float v = mask[base + lane + 32 * k];
        const unsigned m = __ballot_sync(0xffffffffu, v <= 0.5f);
        if (lane == k) dstb[(k + 1) * Hn + y] = m;   // scatter, latency-free
    }
    if (lane == 12) dstb[y] = 0u;                    // zero word-pad j=-1
    if (lane == 13) dstb[13 * Hn + y] = 0u;          // zero word-pad j=12
}

// ---------------- Kernel 2 ----------------
__device__ __forceinline__ float sqrt_approx(float x) {
    float r;
    asm("sqrt.approx.f32 %0, %1;" : "=f"(r) : "f"(x));
    return r;
}

__device__ __forceinline__ float near_far(const float* __restrict__ row,
                                          float best, int i) {
    float df = 5.0f;
    int d = 5;
    const int ip = i + PAD;
    while (df * df < best && d < N) {
#pragma unroll
        for (int u = 0; u < 4; ++u) {
            const int jr = min(ip + d + u, LWD - 1);
            const int jl = max(ip - d - u, 0);
            const float e = df + (float)u;
            best = fminf(best, fmaf(e, e, fminf(row[jr], row[jl])));
        }
        df += 4.0f;
        d += 4;
    }
    return best;
}

__global__ __launch_bounds__(NT, 6) void edt_main(float* __restrict__ out) {
    __shared__ unsigned sh_t[3 * Hn];                 // word-slabs [q][y]
    __shared__ __align__(16) float lines[CPB * LWP];  // 2 padded column-lines
    __shared__ float sh_o[Hn * 3];                    // output stage [y][c], stride 3

    const int t = threadIdx.x;
    const int w = t >> 5, lane = t & 31;
    const int b = blockIdx.x / SPB;
    const int x0 = (blockIdx.x - b * SPB) * CPB;
    const int jw = x0 >> 5;                    // bp0 = x0&31 <= 30, +1 <= 31

    // 1. Load the 3 word-slabs (contiguous, L2-hot) + LARGE pads.
    const unsigned* __restrict__ src = g_bm_t + ((size_t)b * JW + jw) * Hn;
#pragma unroll
    for (int r = 0; r < 3; ++r)
        sh_t[t + NT * r] = src[t + NT * r];
    if (t < CPB * PAD) {
        const int c = t >> 3, o = t & 7;
        lines[c * LWP + o] = LARGE;
        lines[c * LWP + LWD - PAD + o] = LARGE;
    }
    __syncthreads();

    // 2. Row distances: thread owns y=t, 2 columns via funnels.
    {
        const int y = t;
        const unsigned wm1 = sh_t[y];
        const unsigned w0  = sh_t[Hn + y];
        const unsigned wp1 = sh_t[2 * Hn + y];
        const unsigned long long vr = ((unsigned long long)wp1 << 32) | w0;
        const unsigned long long vl = ((unsigned long long)w0 << 32) | wm1;
        const int bp0 = x0 & 31;
        const unsigned* __restrict__ gfb = g_bm_t + (size_t)b * JW * Hn;
#pragma unroll
        for (int xl = 0; xl < CPB; ++xl) {
            const int bp = bp0 + xl;           // <= 31
            const int xg = x0 + xl;
            int dr, dl;
            const unsigned long long r64 = vr >> bp;
            if (r64) {
                dr = __ffsll(r64) - 1;
            } else {                            // rare exact fallback
                dr = 0x7fff;
                for (int j = jw + 2; j < 12; ++j) {
                    const unsigned uu = gfb[(j + 1) * Hn + y];
                    if (uu) { dr = j * 32 - xg + __ffs(uu) - 1; break; }
                }
            }
            const unsigned long long l64 = vl << (31 - bp);
            if (l64) {
                dl = __clzll(l64);
            } else {
                dl = 0x7fff;
                for (int j = jw - 2; j >= 0; --j) {
                    const unsigned uu = gfb[(j + 1) * Hn + y];
                    if (uu) { dl = xg - j * 32 - 31 + __clz(uu); break; }
                }
            }
            const int d = min(dl, dr);
            lines[xl * LWP + PAD + y] = (d < 384) ? (float)(d * d) : LARGE;
        }
    }
    __syncthreads();

    // 3. Column search: pair-shared aligned 12-float window (R16-proven).
    // warp -> (column cl, segment seg); k0 in [0,192); pair p shares the
    // window [4p-4, 4p+7] via 3 aligned LDS.128; sub selects a static
    // 10-float shifted view (FSELs); searches at y0 = 4p+2sub and y0+1.
    const int cl = w & 1, seg = w >> 1;        // seg 0..5
    const int k0 = seg * 32 + lane;            // 0..191
    const int p = k0 >> 1, sub = k0 & 1;
    const float* __restrict__ row = &lines[cl * LWP];

    const float4* __restrict__ vp =
        reinterpret_cast<const float4*>(row + PAD - 4 + 4 * p);
    const float4 A = vp[0], Bq = vp[1], Cq = vp[2];
    const float v[12] = {A.x, A.y, A.z, A.w, Bq.x, Bq.y, Bq.z, Bq.w,
                         Cq.x, Cq.y, Cq.z, Cq.w};
    const bool s1 = (sub != 0);
    const float u0 = s1 ? v[2]  : v[0];
    const float u1 = s1 ? v[3]  : v[1];
    const float u2 = s1 ? v[4]  : v[2];
    const float u3 = s1 ? v[5]  : v[3];
    const float u4 = s1 ? v[6]  : v[4];
    const float u5 = s1 ? v[7]  : v[5];
    const float u6 = s1 ? v[8]  : v[6];
    const float u7 = s1 ? v[9]  : v[7];
    const float u8 = s1 ? v[10] : v[8];
    const float u9 = s1 ? v[11] : v[9];

    float b0, b1;
    {
        const float c1 = fminf(u3, u5) + 1.0f;
        const float c2 = fminf(u2, u6) + 4.0f;
        const float c3 = fminf(u1, u7) + 9.0f;
        const float c4 = fminf(u0, u8) + 16.0f;
        b0 = fminf(u4, fminf(fminf(c1, c2), fminf(c3, c4)));
    }
    {
        const float c1 = fminf(u4, u6) + 1.0f;
        const float c2 = fminf(u3, u7) + 4.0f;
        const float c3 = fminf(u2, u8) + 9.0f;
        const float c4 = fminf(u1, u9) + 16.0f;
        b1 = fminf(u5, fminf(fminf(c1, c2), fminf(c3, c4)));
    }
    const int y0 = 4 * p + 2 * sub;
    if (fmaxf(b0, b1) > 25.0f) {               // rare refinement
        if (b0 > 25.0f) b0 = near_far(row, b0, y0);
        if (b1 > 25.0f) b1 = near_far(row, b1, y0 + 1);
    }

    sh_o[y0 * 3 + cl] = sqrt_approx(b0);
    sh_o[(y0 + 1) * 3 + cl] = sqrt_approx(b1);
    __syncthreads();

    // 4. Tile store: k = t + 384r -> (y = k>>1, c = k&1); 16 sectors/warp.
    float* __restrict__ dst = out + ((size_t)b * Hn) * Wn + x0;
#pragma unroll
    for (int r = 0; r < 2; ++r) {
        const int k = t + NT * r;
        const int y = k >> 1, c = k & 1;
        dst[(size_t)y * Wn + c] = sh_o[y * 3 + c];
    }
}

extern "C" void kernel_launch(void* const* d_in, const int* in_sizes, int n_in,
                              void* d_out, int out_size) {
    const float* mask = (const float*)d_in[0];
    float* out = (float*)d_out;
    (void)in_sizes; (void)n_in; (void)out_size;

    edt_compress<<<Bn * Hn / 12, 384>>>(mask);
    edt_main<<<GRID2, NT>>>(out);
}